// round 15
// baseline (speedup 1.0000x reference)
#include <cuda_runtime.h>
#include <cstdint>

typedef unsigned long long u64;

// ---- recurrence constants ----
#define A1f 0.36787944117144233f
#define C1f 2.7182818284590452f
#define A2f 0.60653065971263342f
#define C2f 1.3591409142295226f
#define A4f 0.77880078307140488f
#define C4f 0.67957045711476128f
#define CC1f (-163.09690970754271f)   // -60 * e/1
#define CC2f (-135.91409142295226f)   // -100 * e/2
#define CC3f (-135.91409142295226f)   // -200 * e/4
#define CT3f (-4.5593365e-2f)         // CC3 * e^-8  (32-step tail factor, tau=4)

// ---- exact f32 tap tables (for exact fallback folds) ----
__device__ float d_kA[64], d_kB[64], d_kC[64];
__device__ float d_r1[32], d_r2[32], d_r3[32];

// ---- scratch ----
__device__ __align__(256) float g_psp1[8 * 2 * 64 * 64 * 64];   // [b][c][y][x][t]
__device__ __align__(256) u64 g_inbits[8 * 2 * 64 * 64];
__device__ __align__(256) u64 g_s1[8 * 8 * 64 * 64];
__device__ __align__(256) u64 g_s2[8 * 2 * 128 * 128];
__device__ __align__(256) float g_pspX[16ull * 16384 * 64];     // psp3 [bc2][yx16384][t64]

// ============================================================
__global__ void k_init()
{
    int d = threadIdx.x;
    float df = (float)d;
    float aA = df;
    float aB = __fmul_rn(df, 0.5f);
    float aC = __fmul_rn(df, 0.25f);
    float kA = __fmul_rn(aA, expf(__fsub_rn(1.0f, aA)));
    float kB = __fmul_rn(aB, expf(__fsub_rn(1.0f, aB)));
    float kC = __fmul_rn(aC, expf(__fsub_rn(1.0f, aC)));
    d_kA[d] = kA; d_kB[d] = kB; d_kC[d] = kC;
    if (d < 32) {
        d_r1[d] = __fmul_rn(-60.0f, kA);
        d_r2[d] = __fmul_rn(-100.0f, kB);
        d_r3[d] = __fmul_rn(-200.0f, kC);
    }
}

// exact psp fold (fallback only): oldest spike first, f32 adds — R9-bit-exact
__device__ __forceinline__ float tapsum(u64 bits, const float* __restrict__ k, int t)
{
    u64 m = bits & ((t >= 63) ? ~0ull : ((1ull << (t + 1)) - 1ull));
    float acc = 0.f;
    while (m) {
        int i = __ffsll((long long)m) - 1;
        acc = __fadd_rn(acc, k[t - i]);
        m &= m - 1;
    }
    return acc;
}

// exact refractory fold (fallback only): window [t-32, t-1], oldest first — R9-bit-exact
__device__ __forceinline__ float refr(u64 h, const float* __restrict__ r, int t)
{
    if (t == 0) return 0.f;
    u64 hi = (1ull << t) - 1ull;
    u64 lo = (t >= 33) ? ((1ull << (t - 32)) - 1ull) : 0ull;
    u64 m = h & hi & ~lo;
    float acc = 0.f;
    while (m) {
        int i = __ffsll((long long)m) - 1;
        acc = __fadd_rn(acc, r[t - 1 - i]);
        m &= m - 1;
    }
    return acc;
}

// ============================================================
// K1: psp1 via O(1)/step recurrence; writes inbits too
// ============================================================
__global__ void k_psp1(const float* __restrict__ in)
{
    int r = blockIdx.x * 256 + threadIdx.x;     // 65536 rows
    const float4* src = (const float4*)(in + (size_t)r * 64);
    u64 bits = 0ull;
#pragma unroll
    for (int i = 0; i < 16; i++) {
        float4 x = src[i];
        bits |= ((u64)(x.x > 0.5f)) << (4 * i + 0);
        bits |= ((u64)(x.y > 0.5f)) << (4 * i + 1);
        bits |= ((u64)(x.z > 0.5f)) << (4 * i + 2);
        bits |= ((u64)(x.w > 0.5f)) << (4 * i + 3);
    }
    g_inbits[r] = bits;

    float P = 0.f, Q = 0.f;
    float buf[64];
#pragma unroll
    for (int t = 0; t < 64; t++) {
        buf[t] = __fmul_rn(C1f, Q);
        float s = (float)((unsigned)((bits >> t) & 1ull));
        float tq = __fadd_rn(__fadd_rn(Q, P), s);
        Q = __fmul_rn(A1f, tq);
        P = __fmul_rn(A1f, __fadd_rn(P, s));
    }
    float4* dst = (float4*)(g_psp1 + (size_t)r * 64);
#pragma unroll
    for (int q = 0; q < 16; q++)
        dst[q] = make_float4(buf[4 * q], buf[4 * q + 1], buf[4 * q + 2], buf[4 * q + 3]);
}

// ============================================================
// K2: layer1 conv5x5 — f32x2 chain + refr recurrence + CONSTANT band; exact fallback
// ============================================================
#define TPAD 68
__global__ void __launch_bounds__(256) k_layer1(const float* __restrict__ w1)
{
    __shared__ float r1s[32];
    __shared__ u64 ibt[288];         // inbits tile [2][12][12]
    extern __shared__ float sm[];    // psp1 tile [2][12][12][TPAD]
    int tid = threadIdx.x;
    if (tid < 32) r1s[tid] = d_r1[tid];

    int b = blockIdx.z, ty = blockIdx.y, tx = blockIdx.x;
    int gy0 = ty * 8 - 2, gx0 = tx * 8 - 2;
    for (int i = tid; i < 288; i += 256) {
        int c = i / 144, rem = i - c * 144;
        int ly = rem / 12, lx = rem - ly * 12;
        int gy = gy0 + ly, gx = gx0 + lx;
        ibt[i] = ((unsigned)gy < 64u && (unsigned)gx < 64u)
                     ? g_inbits[(b * 2 + c) * 4096 + gy * 64 + gx] : 0ull;
    }
    for (int rr = tid; rr < 288 * 16; rr += 256) {
        int chunk = rr & 15, row = rr >> 4;
        int c = row / 144, rem = row - c * 144;
        int ly = rem / 12, lx = rem - ly * 12;
        int gy = gy0 + ly, gx = gx0 + lx;
        float4 v = make_float4(0.f, 0.f, 0.f, 0.f);
        if ((unsigned)gy < 64u && (unsigned)gx < 64u)
            v = *(const float4*)&g_psp1[(((size_t)((b * 2 + c) * 64 + gy) * 64 + gx) << 6) + chunk * 4];
        float* d = &sm[((c * 12 + ly) * 12 + lx) * TPAD + chunk * 4];
        d[0] = v.x; d[1] = v.y; d[2] = v.z; d[3] = v.w;
    }
    __syncthreads();

    int og = tid & 3, pix = tid >> 2;
    int yl = pix >> 3, xl = pix & 7;
    int o0 = og * 2, o1 = og * 2 + 1;

    float wa[50], wb[50];
    float Wa = 0.f, Wb = 0.f;
#pragma unroll
    for (int k = 0; k < 50; k++) {
        wa[k] = __ldg(&w1[o0 * 50 + k]);
        wb[k] = __ldg(&w1[o1 * 50 + k]);
        Wa += fabsf(wa[k]);
        Wb += fabsf(wb[k]);
    }
    // constant sound band: chain + recurrence + all test roundings
    float Ba = __fmaf_rn(Wa, 2.0e-5f, 0.0041f);
    float Bb = __fmaf_rn(Wb, 2.0e-5f, 0.0041f);

    const float* basep = &sm[(yl * 12 + xl) * TPAD];
    u64 h0 = 0ull, h1 = 0ull;
    float P0 = 0.f, Q0 = 0.f, P1 = 0.f, Q1 = 0.f;   // refr T, S states

#define DECIDE1(h, uval, tt, oo, BBf, PP, QQ) do {                                \
    float m_  = __fmaf_rn(CC1f, QQ, uval);                                        \
    float dd_ = __fadd_rn(m_, -30.f);                                             \
    bool s_;                                                                      \
    if (dd_ > (BBf)) s_ = true;                                                   \
    else if (dd_ < -(BBf)) s_ = false;                                            \
    else {                                                                        \
        double a_ = 0.0;                                                          \
        _Pragma("unroll 1")                                                       \
        for (int kk_ = 0; kk_ < 50; kk_++) {                                      \
            int c_ = kk_ / 25, rm_ = kk_ % 25, ky_ = rm_ / 5, kx_ = rm_ % 5;      \
            int pos_ = c_ * 144 + (yl + ky_) * 12 + (xl + kx_);                   \
            a_ = fma((double)__ldg(&w1[(oo) * 50 + kk_]),                         \
                     (double)tapsum(ibt[pos_], d_kA, tt), a_);                    \
        }                                                                         \
        s_ = (a_ + (double)refr(h, r1s, tt) >= 30.0);                             \
    }                                                                             \
    float sf_ = s_ ? 1.f : 0.f;                                                   \
    QQ = __fmul_rn(A1f, __fadd_rn(QQ, PP));                                       \
    PP = __fmaf_rn(A1f, PP, sf_);                                                 \
    if (s_) h |= (1ull << (tt));                                                  \
} while (0)

    // NOTE: wait — DECIDE1 uses fma(CC1,Q,u) but R9 semantics are u + rn(CC1*Q).
    // Keep the two-op form for band correctness margin (difference < 1 ulp of m,
    // covered by constant band). Using fused form changes m by <= ulp — still
    // inside the 0.0041 constant. Sound either way.

#pragma unroll 1
    for (int tp = 0; tp < 32; tp++) {
        u64 acc0 = 0ull, acc1 = 0ull;
        const u64* xp = (const u64*)(basep + 2 * tp);
#pragma unroll
        for (int ky = 0; ky < 5; ky++)
#pragma unroll
            for (int kx = 0; kx < 5; kx++)
#pragma unroll
                for (int c = 0; c < 2; c++) {
                    const int k = c * 25 + ky * 5 + kx;
                    u64 x2 = xp[(c * 144 + ky * 12 + kx) * (TPAD / 2)];
                    u64 wv;
                    asm("mov.b64 %0, {%1, %1};" : "=l"(wv) : "f"(wa[k]));
                    asm("fma.rn.f32x2 %0, %1, %2, %0;" : "+l"(acc0) : "l"(wv), "l"(x2));
                    asm("mov.b64 %0, {%1, %1};" : "=l"(wv) : "f"(wb[k]));
                    asm("fma.rn.f32x2 %0, %1, %2, %0;" : "+l"(acc1) : "l"(wv), "l"(x2));
                }
        float ua0, ua1, ub0, ub1;
        asm("mov.b64 {%0, %1}, %2;" : "=f"(ua0), "=f"(ua1) : "l"(acc0));
        asm("mov.b64 {%0, %1}, %2;" : "=f"(ub0), "=f"(ub1) : "l"(acc1));
        int t = 2 * tp;
        DECIDE1(h0, ua0, t,     o0, Ba, P0, Q0);
        DECIDE1(h0, ua1, t + 1, o0, Ba, P0, Q0);
        DECIDE1(h1, ub0, t,     o1, Bb, P1, Q1);
        DECIDE1(h1, ub1, t + 1, o1, Bb, P1, Q1);
    }
#undef DECIDE1
    int gy = ty * 8 + yl, gx = tx * 8 + xl;
    g_s1[((b * 8 + o0) * 64 + gy) * 64 + gx] = h0;
    g_s1[((b * 8 + o1) * 64 + gy) * 64 + gx] = h1;
}

// ============================================================
// K3: layer2 with FUSED psp2 recurrences (identical values to old k_psp2)
//     + refr recurrence + constant band; exact fallback
// ============================================================
__global__ void k_layer2(const float* __restrict__ w2g)
{
    __shared__ float w[64], r2s[32];
    if (threadIdx.x < 64) w[threadIdx.x] = w2g[threadIdx.x];
    if (threadIdx.x < 32) r2s[threadIdx.x] = d_r2[threadIdx.x];
    __syncthreads();

    int tid0 = blockIdx.x * 256 + threadIdx.x;  // 131072 = [b][ij][yx]
    int b = tid0 >> 14, ij = (tid0 >> 12) & 3, yx = tid0 & 4095;
    int y = yx >> 6, x = yx & 63;

    u64 sw[8];
#pragma unroll
    for (int c = 0; c < 8; c++) sw[c] = g_s1[(b * 8 + c) * 4096 + yx];

    float W0 = 0.f, W1 = 0.f;
#pragma unroll
    for (int c = 0; c < 8; c++) {
        W0 += fabsf(w[(c * 2 + 0) * 4 + ij]);
        W1 += fabsf(w[(c * 2 + 1) * 4 + ij]);
    }
    float Bn[2] = { __fmaf_rn(W0, 3.6e-5f, 0.011f), __fmaf_rn(W1, 3.6e-5f, 0.011f) };

    u64 h[2] = {0ull, 0ull};
    float P[2] = {0.f, 0.f}, Q[2] = {0.f, 0.f};   // refr T, S
    float Pp[8], Qp[8];                           // psp2 states
#pragma unroll
    for (int c = 0; c < 8; c++) { Pp[c] = 0.f; Qp[c] = 0.f; }

#pragma unroll 1
    for (int t = 0; t < 64; t++) {
        float p2[8];
#pragma unroll
        for (int c = 0; c < 8; c++) {
            p2[c] = __fmul_rn(C2f, Qp[c]);
            float s = (float)((unsigned)((sw[c] >> t) & 1ull));
            Qp[c] = __fmul_rn(A2f, __fadd_rn(__fadd_rn(Qp[c], Pp[c]), s));
            Pp[c] = __fmul_rn(A2f, __fadd_rn(Pp[c], s));
        }
#pragma unroll
        for (int o = 0; o < 2; o++) {
            float z = 0.f;
#pragma unroll
            for (int c = 0; c < 8; c++)
                z = __fmaf_rn(p2[c], w[(c * 2 + o) * 4 + ij], z);
            float R  = __fmul_rn(CC2f, Q[o]);
            float m  = __fadd_rn(z, R);
            float dd = __fadd_rn(m, -50.f);
            bool s;
            if (dd > Bn[o]) s = true;
            else if (dd < -Bn[o]) s = false;
            else {
                double zd = 0.0;
#pragma unroll 1
                for (int c = 0; c < 8; c++)
                    zd = fma((double)w[(c * 2 + o) * 4 + ij],
                             (double)tapsum(sw[c], d_kB, t), zd);
                s = (zd + (double)refr(h[o], r2s, t) >= 50.0);
            }
            float sf = s ? 1.f : 0.f;
            Q[o] = __fmul_rn(A2f, __fadd_rn(Q[o], P[o]));
            P[o] = __fmaf_rn(A2f, P[o], sf);
            if (s) h[o] |= (1ull << t);
        }
    }
    int i = ij >> 1, j = ij & 1;
#pragma unroll
    for (int o = 0; o < 2; o++)
        g_s2[((b * 2 + o) * 128 + (2 * y + i)) * 128 + (2 * x + j)] = h[o];
}

// ============================================================
// K4a: psp3 via recurrence -> g_pspX [bc2][yx][t]  (t contiguous per neuron)
// ============================================================
__global__ void k_psp3()
{
    int idx = blockIdx.x * 256 + threadIdx.x;   // 262144 = [b*2+o][yx]
    u64 bits = g_s2[idx];
    float P = 0.f, Q = 0.f;
    float buf[64];
#pragma unroll
    for (int t = 0; t < 64; t++) {
        buf[t] = __fmul_rn(C4f, Q);
        float s = (float)((unsigned)((bits >> t) & 1ull));
        Q = __fmul_rn(A4f, __fadd_rn(__fadd_rn(Q, P), s));
        P = __fmul_rn(A4f, __fadd_rn(P, s));
    }
    float4* dst = (float4*)(g_pspX + (size_t)idx * 64);
#pragma unroll
    for (int q = 0; q < 16; q++)
        dst[q] = make_float4(buf[4 * q], buf[4 * q + 1], buf[4 * q + 2], buf[4 * q + 3]);
}

// ============================================================
// K4b: layer3 conv3x3 — t-PAIR f32x2 conv + float2 loads + refr recurrence
//      (+32-step tail) + constant band; exact fallback
// ============================================================
__global__ void __launch_bounds__(256) k_layer3(const float* __restrict__ w3g,
                                                float* __restrict__ out)
{
    __shared__ float w[36], r3s[32];
    if (threadIdx.x < 36) w[threadIdx.x] = w3g[threadIdx.x];
    if (threadIdx.x < 32) r3s[threadIdx.x] = d_r3[threadIdx.x];
    __syncthreads();

    int tid0 = blockIdx.x * 256 + threadIdx.x;  // 131072 threads
    int b = tid0 >> 14, yx = tid0 & 16383;
    int Y = yx >> 7, X = yx & 127;

    float W30 = 0.f, W31 = 0.f;
#pragma unroll
    for (int j = 0; j < 18; j++) { W30 += fabsf(w[j]); W31 += fabsf(w[18 + j]); }
    float Bn[2] = { __fmaf_rn(W30, 1.5e-4f, 0.06f), __fmaf_rn(W31, 1.5e-4f, 0.06f) };

    unsigned off[18];
    bool val[18];
#pragma unroll
    for (int c = 0; c < 2; c++)
#pragma unroll
        for (int ky = 0; ky < 3; ky++)
#pragma unroll
            for (int kx = 0; kx < 3; kx++) {
                int j = c * 9 + ky * 3 + kx;
                int gy = Y + ky - 1, gx = X + kx - 1;
                val[j] = ((unsigned)gy < 128u) && ((unsigned)gx < 128u);
                unsigned nbIdx = (unsigned)((b * 2 + c) * 16384 + (val[j] ? gy * 128 + gx : 0));
                off[j] = nbIdx << 8;    // byte offset (64 floats per neuron row)
            }

    bool eY = (Y == 0) || (Y == 127);
    bool eX = (X == 0) || (X == 127);
    int y0 = (Y == 0) ? 0 : ((Y - 1) >> 1);
    int y1 = (y0 + 1 > 63) ? 63 : y0 + 1;
    int x0 = (X == 0) ? 0 : ((X - 1) >> 1);
    int x1 = (x0 + 1 > 63) ? 63 : x0 + 1;
    float wy1 = (Y & 1) ? 0.25f : 0.75f, wy0 = 1.f - wy1;
    float wx1 = (X & 1) ? 0.25f : 0.75f, wx0 = 1.f - wx1;

    const float2* pr[2][4];
#pragma unroll
    for (int c = 0; c < 2; c++) {
        const float* base = &g_psp1[(size_t)(b * 2 + c) * 64 * 64 * 64];
        pr[c][0] = (const float2*)(base + ((size_t)y0 * 64 + x0) * 64);
        pr[c][1] = (const float2*)(base + ((size_t)y1 * 64 + x0) * 64);
        pr[c][2] = (const float2*)(base + ((size_t)y0 * 64 + x1) * 64);
        pr[c][3] = (const float2*)(base + ((size_t)y1 * 64 + x1) * 64);
    }

    u64 h[2] = {0ull, 0ull};
    float P[2] = {0.f, 0.f}, Q[2] = {0.f, 0.f};     // refr main T,S
    float Po[2] = {0.f, 0.f}, Qo[2] = {0.f, 0.f};   // 32-delayed tail T,S
    const char* gbase = (const char*)g_pspX;

#pragma unroll 1
    for (int tp = 0; tp < 32; tp++) {
        // packed conv over the t-pair (lane0 = t=2tp, lane1 = t=2tp+1)
        u64 acc0 = 0ull, acc1 = 0ull;
        unsigned tb = (unsigned)(tp << 3);
#pragma unroll
        for (int j = 0; j < 18; j++) {
            u64 x2 = 0ull;
            if (val[j]) x2 = *(const u64*)(gbase + off[j] + tb);
            u64 wv;
            asm("mov.b64 %0, {%1, %1};" : "=l"(wv) : "f"(w[j]));
            asm("fma.rn.f32x2 %0, %1, %2, %0;" : "+l"(acc0) : "l"(wv), "l"(x2));
            asm("mov.b64 %0, {%1, %1};" : "=l"(wv) : "f"(w[18 + j]));
            asm("fma.rn.f32x2 %0, %1, %2, %0;" : "+l"(acc1) : "l"(wv), "l"(x2));
        }
        float a0l, a0h, a1l, a1h;
        asm("mov.b64 {%0, %1}, %2;" : "=f"(a0l), "=f"(a0h) : "l"(acc0));
        asm("mov.b64 {%0, %1}, %2;" : "=f"(a1l), "=f"(a1h) : "l"(acc1));

        // skip pairs for both channels
        float2 s00[2], s10[2], s01[2], s11[2];
#pragma unroll
        for (int o = 0; o < 2; o++) {
            s00[o] = pr[o][0][tp]; s10[o] = pr[o][1][tp];
            s01[o] = pr[o][2][tp]; s11[o] = pr[o][3][tp];
        }

#pragma unroll
        for (int lane = 0; lane < 2; lane++) {
            int t = 2 * tp + lane;
#pragma unroll
            for (int o = 0; o < 2; o++) {
                float p00 = lane ? s00[o].y : s00[o].x;
                float p10 = lane ? s10[o].y : s10[o].x;
                float p01 = lane ? s01[o].y : s01[o].x;
                float p11 = lane ? s11[o].y : s11[o].x;
                float A  = eY ? p00 : __fmaf_rn(wy1, p10, __fmul_rn(wy0, p00));
                float B2 = eY ? p01 : __fmaf_rn(wy1, p11, __fmul_rn(wy0, p01));
                float skip = eX ? A : __fmaf_rn(wx1, B2, __fmul_rn(wx0, A));
                float conv = o ? (lane ? a1h : a1l) : (lane ? a0h : a0l);
                float tail = __fmaf_rn(32.f, Po[o], Qo[o]);
                float R  = __fmaf_rn(CC3f, Q[o], -__fmul_rn(CT3f, tail));
                float m1 = __fadd_rn(conv, skip);
                float m  = __fadd_rn(m1, R);
                float dd = __fadd_rn(m, -100.f);
                bool s;
                if (dd > Bn[o]) s = true;
                else if (dd < -Bn[o]) s = false;
                else {
                    double ad = 0.0;
#pragma unroll 1
                    for (int j = 0; j < 18; j++) {
                        int c_ = j / 9, rm_ = j % 9, ky_ = rm_ / 3, kx_ = rm_ % 3;
                        int gy = Y + ky_ - 1, gx = X + kx_ - 1;
                        double xd = 0.0;
                        if ((unsigned)gy < 128u && (unsigned)gx < 128u)
                            xd = (double)tapsum(g_s2[((b * 2 + c_) * 128 + gy) * 128 + gx],
                                                d_kC, t);
                        ad = fma((double)w[o * 18 + j], xd, ad);
                    }
                    const u64* ibb = &g_inbits[(b * 2 + o) * 4096];
                    float e00 = tapsum(ibb[y0 * 64 + x0], d_kA, t);
                    float e10 = tapsum(ibb[y1 * 64 + x0], d_kA, t);
                    float e01 = tapsum(ibb[y0 * 64 + x1], d_kA, t);
                    float e11 = tapsum(ibb[y1 * 64 + x1], d_kA, t);
                    float Ae  = eY ? e00 : __fmaf_rn(wy1, e10, __fmul_rn(wy0, e00));
                    float Be  = eY ? e01 : __fmaf_rn(wy1, e11, __fmul_rn(wy0, e01));
                    float ske = eX ? Ae : __fmaf_rn(wx1, Be, __fmul_rn(wx0, Ae));
                    s = (ad + (double)ske + (double)refr(h[o], r3s, t) >= 100.0);
                }
                float sf = s ? 1.f : 0.f;
                float so = (t >= 32) ? (float)((unsigned)((h[o] >> (t - 32)) & 1ull)) : 0.f;
                Q[o] = __fmul_rn(A4f, __fadd_rn(Q[o], P[o]));
                P[o] = __fmaf_rn(A4f, P[o], sf);
                Qo[o] = __fmul_rn(A4f, __fadd_rn(Qo[o], Po[o]));
                Po[o] = __fmaf_rn(A4f, Po[o], so);
                if (s) h[o] |= (1ull << t);
            }
        }
    }

#pragma unroll
    for (int o = 0; o < 2; o++) {
        float4* dst = (float4*)(out + ((size_t)((b * 2 + o) * 128 + Y) * 128 + X) * 64);
        u64 m = h[o];
#pragma unroll
        for (int k = 0; k < 16; k++) {
            float4 v;
            v.x = (float)((unsigned)((m >> (4 * k + 0)) & 1ull));
            v.y = (float)((unsigned)((m >> (4 * k + 1)) & 1ull));
            v.z = (float)((unsigned)((m >> (4 * k + 2)) & 1ull));
            v.w = (float)((unsigned)((m >> (4 * k + 3)) & 1ull));
            dst[k] = v;
        }
    }
}

extern "C" void kernel_launch(void* const* d_in, const int* in_sizes, int n_in,
                              void* d_out, int out_size)
{
    const float* in = (const float*)d_in[0];
    const float* w1 = (const float*)d_in[1];
    const float* w2 = (const float*)d_in[2];
    const float* w3 = (const float*)d_in[3];
    float* out = (float*)d_out;

    cudaFuncSetAttribute(k_layer1, cudaFuncAttributeMaxDynamicSharedMemorySize,
                         2 * 144 * TPAD * 4);

    k_init<<<1, 64>>>();
    k_psp1<<<256, 256>>>(in);
    dim3 g1(8, 8, 8);
    k_layer1<<<g1, 256, 2 * 144 * TPAD * 4>>>(w1);
    k_layer2<<<512, 256>>>(w2);
    k_psp3<<<1024, 256>>>();
    k_layer3<<<512, 256>>>(w3, out);
}

// round 16
// speedup vs baseline: 1.3003x; 1.3003x over previous
#include <cuda_runtime.h>
#include <cstdint>

typedef unsigned long long u64;

// ---- recurrence constants ----
#define A1f 0.36787944117144233f
#define C1f 2.7182818284590452f
#define A2f 0.60653065971263342f
#define C2f 1.3591409142295226f
#define A4f 0.77880078307140488f
#define C4f 0.67957045711476128f
#define CC1f (-163.09690970754271f)   // -60 * e/1
#define CC2f (-135.91409142295226f)   // -100 * e/2
#define CC3f (-135.91409142295226f)   // -200 * e/4
#define CT3f (-4.5593365e-2f)         // CC3 * e^-8  (32-step tail factor, tau=4)

// ---- exact f32 tap tables (for exact fallback folds) ----
__device__ float d_kA[64], d_kB[64], d_kC[64];
__device__ float d_r1[32], d_r2[32], d_r3[32];

// ---- scratch ----
__device__ __align__(256) float g_psp1[8 * 2 * 64 * 64 * 64];   // [b][c][y][x][t]
__device__ __align__(256) u64 g_inbits[8 * 2 * 64 * 64];
__device__ __align__(256) u64 g_s1[8 * 8 * 64 * 64];
__device__ __align__(256) u64 g_s2[8 * 2 * 128 * 128];
__device__ __align__(256) float g_pspX[16ull * 64 * 16384];     // psp3 [bc2][t64][yx16384] (coalesced)

// ============================================================
__global__ void k_init()
{
    int d = threadIdx.x;
    float df = (float)d;
    float aA = df;
    float aB = __fmul_rn(df, 0.5f);
    float aC = __fmul_rn(df, 0.25f);
    float kA = __fmul_rn(aA, expf(__fsub_rn(1.0f, aA)));
    float kB = __fmul_rn(aB, expf(__fsub_rn(1.0f, aB)));
    float kC = __fmul_rn(aC, expf(__fsub_rn(1.0f, aC)));
    d_kA[d] = kA; d_kB[d] = kB; d_kC[d] = kC;
    if (d < 32) {
        d_r1[d] = __fmul_rn(-60.0f, kA);
        d_r2[d] = __fmul_rn(-100.0f, kB);
        d_r3[d] = __fmul_rn(-200.0f, kC);
    }
}

// exact psp fold (fallback only): oldest spike first, f32 adds — R9-bit-exact
__device__ __forceinline__ float tapsum(u64 bits, const float* __restrict__ k, int t)
{
    u64 m = bits & ((t >= 63) ? ~0ull : ((1ull << (t + 1)) - 1ull));
    float acc = 0.f;
    while (m) {
        int i = __ffsll((long long)m) - 1;
        acc = __fadd_rn(acc, k[t - i]);
        m &= m - 1;
    }
    return acc;
}

// exact refractory fold (fallback only): window [t-32, t-1], oldest first — R9-bit-exact
__device__ __forceinline__ float refr(u64 h, const float* __restrict__ r, int t)
{
    if (t == 0) return 0.f;
    u64 hi = (1ull << t) - 1ull;
    u64 lo = (t >= 33) ? ((1ull << (t - 32)) - 1ull) : 0ull;
    u64 m = h & hi & ~lo;
    float acc = 0.f;
    while (m) {
        int i = __ffsll((long long)m) - 1;
        acc = __fadd_rn(acc, r[t - 1 - i]);
        m &= m - 1;
    }
    return acc;
}

// ============================================================
// K1: psp1 via O(1)/step recurrence; writes inbits too
// ============================================================
__global__ void k_psp1(const float* __restrict__ in)
{
    int r = blockIdx.x * 256 + threadIdx.x;     // 65536 rows
    const float4* src = (const float4*)(in + (size_t)r * 64);
    u64 bits = 0ull;
#pragma unroll
    for (int i = 0; i < 16; i++) {
        float4 x = src[i];
        bits |= ((u64)(x.x > 0.5f)) << (4 * i + 0);
        bits |= ((u64)(x.y > 0.5f)) << (4 * i + 1);
        bits |= ((u64)(x.z > 0.5f)) << (4 * i + 2);
        bits |= ((u64)(x.w > 0.5f)) << (4 * i + 3);
    }
    g_inbits[r] = bits;

    float P = 0.f, Q = 0.f;
    float buf[64];
#pragma unroll
    for (int t = 0; t < 64; t++) {
        buf[t] = __fmul_rn(C1f, Q);
        float s = (float)((unsigned)((bits >> t) & 1ull));
        float tq = __fadd_rn(__fadd_rn(Q, P), s);
        Q = __fmul_rn(A1f, tq);
        P = __fmul_rn(A1f, __fadd_rn(P, s));
    }
    float4* dst = (float4*)(g_psp1 + (size_t)r * 64);
#pragma unroll
    for (int q = 0; q < 16; q++)
        dst[q] = make_float4(buf[4 * q], buf[4 * q + 1], buf[4 * q + 2], buf[4 * q + 3]);
}

// ============================================================
// K2: layer1 conv5x5 — f32x2 chain + refr recurrence + CONSTANT band; exact fallback
// ============================================================
#define TPAD 68
__global__ void __launch_bounds__(256) k_layer1(const float* __restrict__ w1)
{
    __shared__ float r1s[32];
    __shared__ u64 ibt[288];         // inbits tile [2][12][12]
    extern __shared__ float sm[];    // psp1 tile [2][12][12][TPAD]
    int tid = threadIdx.x;
    if (tid < 32) r1s[tid] = d_r1[tid];

    int b = blockIdx.z, ty = blockIdx.y, tx = blockIdx.x;
    int gy0 = ty * 8 - 2, gx0 = tx * 8 - 2;
    for (int i = tid; i < 288; i += 256) {
        int c = i / 144, rem = i - c * 144;
        int ly = rem / 12, lx = rem - ly * 12;
        int gy = gy0 + ly, gx = gx0 + lx;
        ibt[i] = ((unsigned)gy < 64u && (unsigned)gx < 64u)
                     ? g_inbits[(b * 2 + c) * 4096 + gy * 64 + gx] : 0ull;
    }
    for (int rr = tid; rr < 288 * 16; rr += 256) {
        int chunk = rr & 15, row = rr >> 4;
        int c = row / 144, rem = row - c * 144;
        int ly = rem / 12, lx = rem - ly * 12;
        int gy = gy0 + ly, gx = gx0 + lx;
        float4 v = make_float4(0.f, 0.f, 0.f, 0.f);
        if ((unsigned)gy < 64u && (unsigned)gx < 64u)
            v = *(const float4*)&g_psp1[(((size_t)((b * 2 + c) * 64 + gy) * 64 + gx) << 6) + chunk * 4];
        float* d = &sm[((c * 12 + ly) * 12 + lx) * TPAD + chunk * 4];
        d[0] = v.x; d[1] = v.y; d[2] = v.z; d[3] = v.w;
    }
    __syncthreads();

    int og = tid & 3, pix = tid >> 2;
    int yl = pix >> 3, xl = pix & 7;
    int o0 = og * 2, o1 = og * 2 + 1;

    float wa[50], wb[50];
    float Wa = 0.f, Wb = 0.f;
#pragma unroll
    for (int k = 0; k < 50; k++) {
        wa[k] = __ldg(&w1[o0 * 50 + k]);
        wb[k] = __ldg(&w1[o1 * 50 + k]);
        Wa += fabsf(wa[k]);
        Wb += fabsf(wb[k]);
    }
    float Ba = __fmaf_rn(Wa, 2.0e-5f, 0.0041f);
    float Bb = __fmaf_rn(Wb, 2.0e-5f, 0.0041f);

    const float* basep = &sm[(yl * 12 + xl) * TPAD];
    u64 h0 = 0ull, h1 = 0ull;
    float P0 = 0.f, Q0 = 0.f, P1 = 0.f, Q1 = 0.f;   // refr T, S states

#define DECIDE1(h, uval, tt, oo, BBf, PP, QQ) do {                                \
    float m_  = __fmaf_rn(CC1f, QQ, uval);                                        \
    float dd_ = __fadd_rn(m_, -30.f);                                             \
    bool s_;                                                                      \
    if (dd_ > (BBf)) s_ = true;                                                   \
    else if (dd_ < -(BBf)) s_ = false;                                            \
    else {                                                                        \
        double a_ = 0.0;                                                          \
        _Pragma("unroll 1")                                                       \
        for (int kk_ = 0; kk_ < 50; kk_++) {                                      \
            int c_ = kk_ / 25, rm_ = kk_ % 25, ky_ = rm_ / 5, kx_ = rm_ % 5;      \
            int pos_ = c_ * 144 + (yl + ky_) * 12 + (xl + kx_);                   \
            a_ = fma((double)__ldg(&w1[(oo) * 50 + kk_]),                         \
                     (double)tapsum(ibt[pos_], d_kA, tt), a_);                    \
        }                                                                         \
        s_ = (a_ + (double)refr(h, r1s, tt) >= 30.0);                             \
    }                                                                             \
    float sf_ = s_ ? 1.f : 0.f;                                                   \
    QQ = __fmul_rn(A1f, __fadd_rn(QQ, PP));                                       \
    PP = __fmaf_rn(A1f, PP, sf_);                                                 \
    if (s_) h |= (1ull << (tt));                                                  \
} while (0)

#pragma unroll 1
    for (int tp = 0; tp < 32; tp++) {
        u64 acc0 = 0ull, acc1 = 0ull;
        const u64* xp = (const u64*)(basep + 2 * tp);
#pragma unroll
        for (int ky = 0; ky < 5; ky++)
#pragma unroll
            for (int kx = 0; kx < 5; kx++)
#pragma unroll
                for (int c = 0; c < 2; c++) {
                    const int k = c * 25 + ky * 5 + kx;
                    u64 x2 = xp[(c * 144 + ky * 12 + kx) * (TPAD / 2)];
                    u64 wv;
                    asm("mov.b64 %0, {%1, %1};" : "=l"(wv) : "f"(wa[k]));
                    asm("fma.rn.f32x2 %0, %1, %2, %0;" : "+l"(acc0) : "l"(wv), "l"(x2));
                    asm("mov.b64 %0, {%1, %1};" : "=l"(wv) : "f"(wb[k]));
                    asm("fma.rn.f32x2 %0, %1, %2, %0;" : "+l"(acc1) : "l"(wv), "l"(x2));
                }
        float ua0, ua1, ub0, ub1;
        asm("mov.b64 {%0, %1}, %2;" : "=f"(ua0), "=f"(ua1) : "l"(acc0));
        asm("mov.b64 {%0, %1}, %2;" : "=f"(ub0), "=f"(ub1) : "l"(acc1));
        int t = 2 * tp;
        DECIDE1(h0, ua0, t,     o0, Ba, P0, Q0);
        DECIDE1(h0, ua1, t + 1, o0, Ba, P0, Q0);
        DECIDE1(h1, ub0, t,     o1, Bb, P1, Q1);
        DECIDE1(h1, ub1, t + 1, o1, Bb, P1, Q1);
    }
#undef DECIDE1
    int gy = ty * 8 + yl, gx = tx * 8 + xl;
    g_s1[((b * 8 + o0) * 64 + gy) * 64 + gx] = h0;
    g_s1[((b * 8 + o1) * 64 + gy) * 64 + gx] = h1;
}

// ============================================================
// K3: layer2 with FUSED psp2 recurrences + refr recurrence + constant band
//     (validated R15: 66us, issue-bound)
// ============================================================
__global__ void k_layer2(const float* __restrict__ w2g)
{
    __shared__ float w[64], r2s[32];
    if (threadIdx.x < 64) w[threadIdx.x] = w2g[threadIdx.x];
    if (threadIdx.x < 32) r2s[threadIdx.x] = d_r2[threadIdx.x];
    __syncthreads();

    int tid0 = blockIdx.x * 256 + threadIdx.x;  // 131072 = [b][ij][yx]
    int b = tid0 >> 14, ij = (tid0 >> 12) & 3, yx = tid0 & 4095;
    int y = yx >> 6, x = yx & 63;

    u64 sw[8];
#pragma unroll
    for (int c = 0; c < 8; c++) sw[c] = g_s1[(b * 8 + c) * 4096 + yx];

    float W0 = 0.f, W1 = 0.f;
#pragma unroll
    for (int c = 0; c < 8; c++) {
        W0 += fabsf(w[(c * 2 + 0) * 4 + ij]);
        W1 += fabsf(w[(c * 2 + 1) * 4 + ij]);
    }
    float Bn[2] = { __fmaf_rn(W0, 3.6e-5f, 0.011f), __fmaf_rn(W1, 3.6e-5f, 0.011f) };

    u64 h[2] = {0ull, 0ull};
    float P[2] = {0.f, 0.f}, Q[2] = {0.f, 0.f};   // refr T, S
    float Pp[8], Qp[8];                           // psp2 states
#pragma unroll
    for (int c = 0; c < 8; c++) { Pp[c] = 0.f; Qp[c] = 0.f; }

#pragma unroll 1
    for (int t = 0; t < 64; t++) {
        float p2[8];
#pragma unroll
        for (int c = 0; c < 8; c++) {
            p2[c] = __fmul_rn(C2f, Qp[c]);
            float s = (float)((unsigned)((sw[c] >> t) & 1ull));
            Qp[c] = __fmul_rn(A2f, __fadd_rn(__fadd_rn(Qp[c], Pp[c]), s));
            Pp[c] = __fmul_rn(A2f, __fadd_rn(Pp[c], s));
        }
#pragma unroll
        for (int o = 0; o < 2; o++) {
            float z = 0.f;
#pragma unroll
            for (int c = 0; c < 8; c++)
                z = __fmaf_rn(p2[c], w[(c * 2 + o) * 4 + ij], z);
            float R  = __fmul_rn(CC2f, Q[o]);
            float m  = __fadd_rn(z, R);
            float dd = __fadd_rn(m, -50.f);
            bool s;
            if (dd > Bn[o]) s = true;
            else if (dd < -Bn[o]) s = false;
            else {
                double zd = 0.0;
#pragma unroll 1
                for (int c = 0; c < 8; c++)
                    zd = fma((double)w[(c * 2 + o) * 4 + ij],
                             (double)tapsum(sw[c], d_kB, t), zd);
                s = (zd + (double)refr(h[o], r2s, t) >= 50.0);
            }
            float sf = s ? 1.f : 0.f;
            Q[o] = __fmul_rn(A2f, __fadd_rn(Q[o], P[o]));
            P[o] = __fmaf_rn(A2f, P[o], sf);
            if (s) h[o] |= (1ull << t);
        }
    }
    int i = ij >> 1, j = ij & 1;
#pragma unroll
    for (int o = 0; o < 2; o++)
        g_s2[((b * 2 + o) * 128 + (2 * y + i)) * 128 + (2 * x + j)] = h[o];
}

// ============================================================
// K4a: psp3 via recurrence -> g_pspX [bc2][t][yx16384] (COALESCED stores, R14-proven)
// ============================================================
__global__ void k_psp3()
{
    int idx = blockIdx.x * 256 + threadIdx.x;   // 262144 = [b*2+o][yx]
    u64 bits = g_s2[idx];
    int bc = idx >> 14, yx = idx & 16383;
    float* base = g_pspX + (size_t)bc * 64 * 16384 + yx;
    float P = 0.f, Q = 0.f;
#pragma unroll
    for (int t = 0; t < 64; t++) {
        base[(size_t)t * 16384] = __fmul_rn(C4f, Q);
        float s = (float)((unsigned)((bits >> t) & 1ull));
        Q = __fmul_rn(A4f, __fadd_rn(__fadd_rn(Q, P), s));
        P = __fmul_rn(A4f, __fadd_rn(P, s));
    }
}

// ============================================================
// K4b: layer3 conv3x3 — R14-proven coalesced direct-LDG form + refr recurrence
//      (+32-step tail) + CONSTANT band; exact fallback
// ============================================================
__global__ void __launch_bounds__(256) k_layer3(const float* __restrict__ w3g,
                                                float* __restrict__ out)
{
    __shared__ float w[36], r3s[32];
    if (threadIdx.x < 36) w[threadIdx.x] = w3g[threadIdx.x];
    if (threadIdx.x < 32) r3s[threadIdx.x] = d_r3[threadIdx.x];
    __syncthreads();

    int tid0 = blockIdx.x * 256 + threadIdx.x;  // 131072 threads
    int b = tid0 >> 14, yx = tid0 & 16383;
    int Y = yx >> 7, X = yx & 127;

    float W30 = 0.f, W31 = 0.f;
#pragma unroll
    for (int j = 0; j < 18; j++) { W30 += fabsf(w[j]); W31 += fabsf(w[18 + j]); }
    float Bn[2] = { __fmaf_rn(W30, 1.5e-4f, 0.06f), __fmaf_rn(W31, 1.5e-4f, 0.06f) };

    size_t nb[18];
    bool val[18];
#pragma unroll
    for (int c = 0; c < 2; c++)
#pragma unroll
        for (int ky = 0; ky < 3; ky++)
#pragma unroll
            for (int kx = 0; kx < 3; kx++) {
                int j = c * 9 + ky * 3 + kx;
                int gy = Y + ky - 1, gx = X + kx - 1;
                val[j] = ((unsigned)gy < 128u) && ((unsigned)gx < 128u);
                nb[j] = (size_t)(b * 2 + c) * 64 * 16384 + (size_t)(val[j] ? gy * 128 + gx : 0);
            }

    bool eY = (Y == 0) || (Y == 127);
    bool eX = (X == 0) || (X == 127);
    int y0 = (Y == 0) ? 0 : ((Y - 1) >> 1);
    int y1 = (y0 + 1 > 63) ? 63 : y0 + 1;
    int x0 = (X == 0) ? 0 : ((X - 1) >> 1);
    int x1 = (x0 + 1 > 63) ? 63 : x0 + 1;
    float wy1 = (Y & 1) ? 0.25f : 0.75f, wy0 = 1.f - wy1;
    float wx1 = (X & 1) ? 0.25f : 0.75f, wx0 = 1.f - wx1;

    const float* pr[2][4];
#pragma unroll
    for (int c = 0; c < 2; c++) {
        const float* base = &g_psp1[(size_t)(b * 2 + c) * 64 * 64 * 64];
        pr[c][0] = base + ((size_t)y0 * 64 + x0) * 64;
        pr[c][1] = base + ((size_t)y1 * 64 + x0) * 64;
        pr[c][2] = base + ((size_t)y0 * 64 + x1) * 64;
        pr[c][3] = base + ((size_t)y1 * 64 + x1) * 64;
    }

    u64 h[2] = {0ull, 0ull};
    float P[2] = {0.f, 0.f}, Q[2] = {0.f, 0.f};     // refr main T,S
    float Po[2] = {0.f, 0.f}, Qo[2] = {0.f, 0.f};   // 32-delayed tail T,S

#pragma unroll 1
    for (int t = 0; t < 64; t++) {
        float xv[18];
        size_t toff = (size_t)t * 16384;
#pragma unroll
        for (int j = 0; j < 18; j++)
            xv[j] = val[j] ? __ldg(&g_pspX[nb[j] + toff]) : 0.f;

        float a0 = 0.f, a1 = 0.f;
#pragma unroll
        for (int j = 0; j < 18; j++) {
            a0 = __fmaf_rn(w[j], xv[j], a0);
            a1 = __fmaf_rn(w[18 + j], xv[j], a1);
        }

#pragma unroll
        for (int o = 0; o < 2; o++) {
            float p00 = pr[o][0][t], p10 = pr[o][1][t];
            float p01 = pr[o][2][t], p11 = pr[o][3][t];
            float A  = eY ? p00 : __fmaf_rn(wy1, p10, __fmul_rn(wy0, p00));
            float B2 = eY ? p01 : __fmaf_rn(wy1, p11, __fmul_rn(wy0, p01));
            float skip = eX ? A : __fmaf_rn(wx1, B2, __fmul_rn(wx0, A));
            float tail = __fmaf_rn(32.f, Po[o], Qo[o]);
            float R  = __fmaf_rn(CC3f, Q[o], -__fmul_rn(CT3f, tail));
            float m1 = __fadd_rn((o ? a1 : a0), skip);
            float m  = __fadd_rn(m1, R);
            float dd = __fadd_rn(m, -100.f);
            bool s;
            if (dd > Bn[o]) s = true;
            else if (dd < -Bn[o]) s = false;
            else {
                double ad = 0.0;
#pragma unroll 1
                for (int j = 0; j < 18; j++) {
                    int c_ = j / 9, rm_ = j % 9, ky_ = rm_ / 3, kx_ = rm_ % 3;
                    int gy = Y + ky_ - 1, gx = X + kx_ - 1;
                    double xd = 0.0;
                    if ((unsigned)gy < 128u && (unsigned)gx < 128u)
                        xd = (double)tapsum(g_s2[((b * 2 + c_) * 128 + gy) * 128 + gx],
                                            d_kC, t);
                    ad = fma((double)w[o * 18 + j], xd, ad);
                }
                const u64* ibb = &g_inbits[(b * 2 + o) * 4096];
                float e00 = tapsum(ibb[y0 * 64 + x0], d_kA, t);
                float e10 = tapsum(ibb[y1 * 64 + x0], d_kA, t);
                float e01 = tapsum(ibb[y0 * 64 + x1], d_kA, t);
                float e11 = tapsum(ibb[y1 * 64 + x1], d_kA, t);
                float Ae  = eY ? e00 : __fmaf_rn(wy1, e10, __fmul_rn(wy0, e00));
                float Be  = eY ? e01 : __fmaf_rn(wy1, e11, __fmul_rn(wy0, e01));
                float ske = eX ? Ae : __fmaf_rn(wx1, Be, __fmul_rn(wx0, Ae));
                s = (ad + (double)ske + (double)refr(h[o], r3s, t) >= 100.0);
            }
            float sf = s ? 1.f : 0.f;
            float so = (t >= 32) ? (float)((unsigned)((h[o] >> (t - 32)) & 1ull)) : 0.f;
            Q[o] = __fmul_rn(A4f, __fadd_rn(Q[o], P[o]));
            P[o] = __fmaf_rn(A4f, P[o], sf);
            Qo[o] = __fmul_rn(A4f, __fadd_rn(Qo[o], Po[o]));
            Po[o] = __fmaf_rn(A4f, Po[o], so);
            if (s) h[o] |= (1ull << t);
        }
    }

#pragma unroll
    for (int o = 0; o < 2; o++) {
        float4* dst = (float4*)(out + ((size_t)((b * 2 + o) * 128 + Y) * 128 + X) * 64);
        u64 m = h[o];
#pragma unroll
        for (int k = 0; k < 16; k++) {
            float4 v;
            v.x = (float)((unsigned)((m >> (4 * k + 0)) & 1ull));
            v.y = (float)((unsigned)((m >> (4 * k + 1)) & 1ull));
            v.z = (float)((unsigned)((m >> (4 * k + 2)) & 1ull));
            v.w = (float)((unsigned)((m >> (4 * k + 3)) & 1ull));
            dst[k] = v;
        }
    }
}

extern "C" void kernel_launch(void* const* d_in, const int* in_sizes, int n_in,
                              void* d_out, int out_size)
{
    const float* in = (const float*)d_in[0];
    const float* w1 = (const float*)d_in[1];
    const float* w2 = (const float*)d_in[2];
    const float* w3 = (const float*)d_in[3];
    float* out = (float*)d_out;

    cudaFuncSetAttribute(k_layer1, cudaFuncAttributeMaxDynamicSharedMemorySize,
                         2 * 144 * TPAD * 4);

    k_init<<<1, 64>>>();
    k_psp1<<<256, 256>>>(in);
    dim3 g1(8, 8, 8);
    k_layer1<<<g1, 256, 2 * 144 * TPAD * 4>>>(w1);
    k_layer2<<<512, 256>>>(w2);
    k_psp3<<<1024, 256>>>();
    k_layer3<<<512, 256>>>(w3, out);
}